// round 2
// baseline (speedup 1.0000x reference)
#include <cuda_runtime.h>
#include <stdint.h>

// SNU: out[b,h,t] = spike recurrence over xw[t,b,h] = sum_i x[b,i,t] * W[i,h]
// B=128, I=512, H=512, T=512.  DECAY=0.8
//
// Phase 1: fp32 SGEMM (M=B*T=65536, N=H=512, K=I=512) using packed fma.rn.f32x2
//          into scratch g_xw laid out [(b*T+t)][h]  (h contiguous).
// Phase 2: per-(b,h) sequential recurrence over t with SMEM transpose for
//          coalesced [b][h][t] output stores.

typedef unsigned long long ull;

__device__ float g_xw[33554432];   // 65536 x 512 floats = 134 MB scratch

// ---------------------------------------------------------------------------
// GEMM: C[m*512 + n] = sum_k X[b*262144 + k*512 + t] * W[k*512 + n]
// where m = b*512 + t.  Tiles: BM=BN=128, BK=8, 256 threads, 8x8 microtile.
// Accumulators packed as f32x2 pairs along N -> fma.rn.f32x2 (2 FMA/instr).
// ---------------------------------------------------------------------------
__global__ __launch_bounds__(256, 2) void gemm_kernel(
    const float* __restrict__ X, const float* __restrict__ W)
{
    __shared__ float As[2][8][128];
    __shared__ float Bs[2][8][128];

    const int bn = blockIdx.x * 128;          // N offset
    const int m0 = blockIdx.y * 128;          // M offset
    const int batch = m0 >> 9;                // T=512 divides tiles: one b per tile
    const int t0 = m0 & 511;

    const float* Xb = X + (size_t)batch * 262144 + t0;  // + k*512 + mm
    const float* Wb = W + bn;                            // + k*512 + nn

    const int tid = threadIdx.x;
    const int lk = tid >> 5;                  // 0..7   (k within tile)
    const int lv = (tid & 31) * 4;            // 0..124 (m or n, float4)

    const int tx = tid & 15;                  // n microtile
    const int ty = tid >> 4;                  // m microtile

    ull c2[8][4];
    #pragma unroll
    for (int i = 0; i < 8; i++)
        #pragma unroll
        for (int j = 0; j < 4; j++) c2[i][j] = 0ull;

    // preload tile 0
    float4 ra = *(const float4*)(Xb + lk * 512 + lv);
    float4 rb = *(const float4*)(Wb + lk * 512 + lv);
    *(float4*)&As[0][lk][lv] = ra;
    *(float4*)&Bs[0][lk][lv] = rb;
    __syncthreads();

    int buf = 0;
    #pragma unroll 1
    for (int k0 = 0; k0 < 512; k0 += 8) {
        const bool has_next = (k0 + 8) < 512;
        if (has_next) {
            ra = *(const float4*)(Xb + (size_t)(k0 + 8 + lk) * 512 + lv);
            rb = *(const float4*)(Wb + (size_t)(k0 + 8 + lk) * 512 + lv);
        }
        #pragma unroll
        for (int kk = 0; kk < 8; kk++) {
            float4 a0 = *(const float4*)&As[buf][kk][ty * 8];
            float4 a1 = *(const float4*)&As[buf][kk][ty * 8 + 4];
            const ull* bp = (const ull*)&Bs[buf][kk][tx * 8];
            ull b0 = bp[0], b1 = bp[1], b2v = bp[2], b3 = bp[3];
            float av[8] = {a0.x, a0.y, a0.z, a0.w, a1.x, a1.y, a1.z, a1.w};
            #pragma unroll
            for (int i = 0; i < 8; i++) {
                ull a2;
                asm("mov.b64 %0, {%1, %1};" : "=l"(a2) : "f"(av[i]));
                asm("fma.rn.f32x2 %0, %1, %2, %0;" : "+l"(c2[i][0]) : "l"(a2), "l"(b0));
                asm("fma.rn.f32x2 %0, %1, %2, %0;" : "+l"(c2[i][1]) : "l"(a2), "l"(b1));
                asm("fma.rn.f32x2 %0, %1, %2, %0;" : "+l"(c2[i][2]) : "l"(a2), "l"(b2v));
                asm("fma.rn.f32x2 %0, %1, %2, %0;" : "+l"(c2[i][3]) : "l"(a2), "l"(b3));
            }
        }
        if (has_next) {
            *(float4*)&As[buf ^ 1][lk][lv] = ra;
            *(float4*)&Bs[buf ^ 1][lk][lv] = rb;
            __syncthreads();
            buf ^= 1;
        }
    }

    // epilogue: packed pair == two consecutive fp32 -> store as 8B words
    #pragma unroll
    for (int i = 0; i < 8; i++) {
        ull* dst = (ull*)(g_xw + (size_t)(m0 + ty * 8 + i) * 512 + bn + tx * 8);
        #pragma unroll
        for (int j = 0; j < 4; j++) dst[j] = c2[i][j];
    }
}

// ---------------------------------------------------------------------------
// Recurrence: h = relu(xw_t + 0.8*h*(1-y));  y = (h + bias > 0)
// out[b][h][t] = y.  One thread per (b,h) lane; SMEM-staged transposed stores.
// ---------------------------------------------------------------------------
__global__ __launch_bounds__(128) void recur_kernel(
    const float* __restrict__ bias, float* __restrict__ out)
{
    const int b  = blockIdx.x >> 2;
    const int h0 = (blockIdx.x & 3) * 128;
    const int h  = h0 + threadIdx.x;

    const float bb = bias[h];
    float hs = 0.0f, y = 0.0f;

    const float* p  = g_xw + (size_t)b * 262144 + h;          // + t*512
    float*       po = out + ((size_t)b * 512 + h0) * 512;     // row base

    __shared__ float buf[128][33];

    for (int tc = 0; tc < 512; tc += 32) {
        #pragma unroll
        for (int j = 0; j < 32; j++) {
            float v = p[(size_t)(tc + j) * 512];
            // (1-y) is exactly 0 or 1, so this matches the reference bitwise
            // given identical xw.
            hs = fmaxf(v + 0.8f * hs * (1.0f - y), 0.0f);
            y  = (hs + bb > 0.0f) ? 1.0f : 0.0f;
            buf[threadIdx.x][j] = y;
        }
        __syncthreads();
        const int r = threadIdx.x >> 5;   // 0..3
        const int c = threadIdx.x & 31;   // 0..31
        #pragma unroll
        for (int rr = 0; rr < 128; rr += 4)
            po[(size_t)(rr + r) * 512 + tc + c] = buf[rr + r][c];
        __syncthreads();
    }
}

extern "C" void kernel_launch(void* const* d_in, const int* in_sizes, int n_in,
                              void* d_out, int out_size)
{
    const float* x = (const float*)d_in[0];   // (B, I, T) = (128, 512, 512)
    const float* W = (const float*)d_in[1];   // (I, H)    = (512, 512)
    const float* b = (const float*)d_in[2];   // (1, H)    = (512,)
    float* out = (float*)d_out;               // (B, H, T) float32

    gemm_kernel<<<dim3(4, 512), 256>>>(x, W);
    recur_kernel<<<512, 128>>>(b, out);
}

// round 7
// speedup vs baseline: 1.4677x; 1.4677x over previous
#include <cuda_runtime.h>
#include <cuda_fp16.h>
#include <stdint.h>

// SNU on GB300 (target sm_103 base ISA — no tcgen05):
//   out[b,h,t] = spike recurrence over xw[t,b,h] = sum_i x[b,i,t]*W[i,h]
//   B=128, I=512, H=512, T=512, DECAY=0.8
//
// Phase 1: transpose+split x [b][i][t] -> fp16 pair (a0,a1) in [b][t][i];
//          W [i][h] -> fp16 pair (b0,b1) in [h][i].   a = a0+a1 (22 mantissa bits)
// Phase 2: mma.sync m16n8k16 fp16->fp32 GEMM with K extended to 3*512:
//          seg0 a0*b0, seg1 a0*b1, seg2 a1*b0  (dropped a1*b1 ~ 2^-24 rel)
//          -> g_xw[m=(b,t)][h] fp32.  Total error ~1e-6 abs (= fp32 noise level).
// Phase 3: sequential spike recurrence (identical to round-2 fp32 version).

typedef unsigned long long ull;

__device__ float  g_xw[33554432];                 // 65536 x 512 fp32
__device__ __half g_a0[33554432], g_a1[33554432]; // 65536 x 512 fp16 splits of x^T
__device__ __half g_b0[262144],  g_b1[262144];    // 512 x 512 fp16 splits of W^T

// ---------------------------------------------------------------- helpers ---
__device__ __forceinline__ uint32_t smem_u32(const void* p) {
    uint32_t a;
    asm("{ .reg .u64 t; cvta.to.shared.u64 t, %1; cvt.u32.u64 %0, t; }"
        : "=r"(a) : "l"(p));
    return a;
}
__device__ __forceinline__ void cp16(uint32_t dst, const void* src) {
    asm volatile("cp.async.cg.shared.global [%0], [%1], 16;"
                 :: "r"(dst), "l"(src) : "memory");
}
__device__ __forceinline__ void ldsm4(uint32_t a, uint32_t& r0, uint32_t& r1,
                                      uint32_t& r2, uint32_t& r3) {
    asm volatile("ldmatrix.sync.aligned.m8n8.x4.shared.b16 {%0,%1,%2,%3}, [%4];"
                 : "=r"(r0), "=r"(r1), "=r"(r2), "=r"(r3) : "r"(a));
}
__device__ __forceinline__ void mma16816(float* d, const uint32_t* a,
                                         uint32_t b0, uint32_t b1) {
    asm volatile(
        "mma.sync.aligned.m16n8k16.row.col.f32.f16.f16.f32 "
        "{%0,%1,%2,%3}, {%4,%5,%6,%7}, {%8,%9}, {%0,%1,%2,%3};"
        : "+f"(d[0]), "+f"(d[1]), "+f"(d[2]), "+f"(d[3])
        : "r"(a[0]), "r"(a[1]), "r"(a[2]), "r"(a[3]), "r"(b0), "r"(b1));
}

// ------------------------------------------------------------ convert pass ---
// Transpose 64x64 tile of src[R][C] (row stride 512) into dst[C][R], 2-way
// fp16 split:  v = h0 + h1 + eps,  |eps| <= 2^-23 |v|.
__device__ __forceinline__ void trans_split2(
    const float* __restrict__ src, size_t src_off, size_t dst_off,
    int r0, int c0, __half* __restrict__ d0, __half* __restrict__ d1,
    float smtile[64][65])
{
    const float* sp = src + src_off + (size_t)r0 * 512 + c0;
    for (int e = threadIdx.x; e < 1024; e += 256) {
        int r = e >> 4, c = (e & 15) << 2;
        float4 v = *(const float4*)(sp + (size_t)r * 512 + c);
        smtile[r][c] = v.x; smtile[r][c + 1] = v.y;
        smtile[r][c + 2] = v.z; smtile[r][c + 3] = v.w;
    }
    __syncthreads();
    size_t ob = dst_off + (size_t)c0 * 512 + r0;
    for (int e = threadIdx.x; e < 1024; e += 256) {
        int r = e >> 4, c = (e & 15) << 2;
        union { __half h[4]; ull u; } p0, p1;
        #pragma unroll
        for (int q = 0; q < 4; q++) {
            float v = smtile[c + q][r];
            __half h0 = __float2half_rn(v);
            float rr = v - __half2float(h0);
            __half h1 = __float2half_rn(rr);
            p0.h[q] = h0; p1.h[q] = h1;
        }
        size_t o = ob + (size_t)r * 512 + c;
        *(ull*)(d0 + o) = p0.u;
        *(ull*)(d1 + o) = p1.u;
    }
    __syncthreads();
}

__global__ __launch_bounds__(256) void convert_x_kernel(const float* __restrict__ x) {
    __shared__ float tile[64][65];
    size_t boff = (size_t)blockIdx.z * 262144;
    trans_split2(x, boff, boff, blockIdx.y * 64, blockIdx.x * 64, g_a0, g_a1, tile);
}
__global__ __launch_bounds__(256) void convert_w_kernel(const float* __restrict__ W) {
    __shared__ float tile[64][65];
    trans_split2(W, 0, 0, blockIdx.y * 64, blockIdx.x * 64, g_b0, g_b1, tile);
}

// --------------------------------------------------------------- GEMM pass ---
// C[m][n] over effective K=1536 (3 segments of 512).
// CTA tile 128(M) x 128(N) x 32(K-chunk). 256 threads = 8 warps (4m x 2n),
// warp tile 32x64. 4-stage cp.async pipeline.
// SMEM per stage: A 128x40 halves (80B pitch, conflict-free ldmatrix) + B same
// = 20480 B; 4 stages = 81920 B.

#define STG_B   20480
#define BPITCH  40

__global__ __launch_bounds__(256, 2) void gemm_hmma() {
    extern __shared__ __half smraw[];
    const uint32_t smb = smem_u32(smraw);

    const int tid  = threadIdx.x;
    const int n0   = blockIdx.x * 128;
    const int m0   = blockIdx.y * 128;
    const int wid  = tid >> 5, lane = tid & 31;
    const int mw   = (wid >> 1) * 32;
    const int nw   = (wid & 1) * 64;

    float acc[2][8][4];
    #pragma unroll
    for (int i = 0; i < 2; i++)
        #pragma unroll
        for (int j = 0; j < 8; j++)
            #pragma unroll
            for (int q = 0; q < 4; q++) acc[i][j][q] = 0.0f;

    const int lrow = tid >> 1;          // 0..127
    const int lch  = (tid & 1) * 2;     // 16B-chunk index {0,2} within 64B row

    // chunk c (0..47): K segment = c>>4, local k = (c&15)*32
    #define LOAD_CHUNK(c, slot) do {                                          \
        int _seg  = (c) >> 4;                                                 \
        int _kloc = ((c) & 15) << 5;                                          \
        const __half* _ap = (_seg == 2) ? g_a1 : g_a0;                        \
        const __half* _bp = (_seg == 1) ? g_b1 : g_b0;                        \
        uint32_t _sA = smb + (slot) * STG_B + (lrow * BPITCH + lch * 8) * 2;  \
        const __half* _ag = _ap + (size_t)(m0 + lrow) * 512 + _kloc + lch * 8;\
        const __half* _bg = _bp + (size_t)(n0 + lrow) * 512 + _kloc + lch * 8;\
        cp16(_sA,          _ag);  cp16(_sA + 16,          _ag + 8);           \
        cp16(_sA + 10240,  _bg);  cp16(_sA + 10240 + 16,  _bg + 8);           \
    } while (0)

    LOAD_CHUNK(0, 0); asm volatile("cp.async.commit_group;" ::: "memory");
    LOAD_CHUNK(1, 1); asm volatile("cp.async.commit_group;" ::: "memory");
    LOAD_CHUNK(2, 2); asm volatile("cp.async.commit_group;" ::: "memory");

    for (int i = 0; i < 48; i++) {
        asm volatile("cp.async.wait_group 2;" ::: "memory");
        __syncthreads();
        if (i + 3 < 48) LOAD_CHUNK(i + 3, (i + 3) & 3);
        asm volatile("cp.async.commit_group;" ::: "memory");

        const uint32_t base = smb + (i & 3) * STG_B;
        #pragma unroll
        for (int ks = 0; ks < 2; ks++) {
            const int col = ks * 16 + (lane >> 4) * 8;
            uint32_t ar[2][4], br[4][4];
            #pragma unroll
            for (int mi = 0; mi < 2; mi++) {
                int row = mw + mi * 16 + (lane & 15);
                ldsm4(base + (row * BPITCH + col) * 2,
                      ar[mi][0], ar[mi][1], ar[mi][2], ar[mi][3]);
            }
            #pragma unroll
            for (int nb = 0; nb < 4; nb++) {
                int row = nw + nb * 16 + (lane & 15);
                ldsm4(base + 10240 + (row * BPITCH + col) * 2,
                      br[nb][0], br[nb][1], br[nb][2], br[nb][3]);
            }
            #pragma unroll
            for (int mi = 0; mi < 2; mi++)
                #pragma unroll
                for (int nf = 0; nf < 8; nf++) {
                    int nb = nf >> 1, hh = nf & 1;
                    mma16816(acc[mi][nf], ar[mi], br[nb][hh], br[nb][hh + 2]);
                }
        }
    }

    // epilogue: d-frag thread map: (m = lane/4 [+8], n = 2*(lane%4) [+1])
    #pragma unroll
    for (int mi = 0; mi < 2; mi++) {
        int row = m0 + mw + mi * 16 + (lane >> 2);
        #pragma unroll
        for (int nf = 0; nf < 8; nf++) {
            int col = n0 + nw + nf * 8 + ((lane & 3) << 1);
            float2 v0 = make_float2(acc[mi][nf][0], acc[mi][nf][1]);
            float2 v1 = make_float2(acc[mi][nf][2], acc[mi][nf][3]);
            *(float2*)(g_xw + (size_t)row * 512 + col)       = v0;
            *(float2*)(g_xw + (size_t)(row + 8) * 512 + col) = v1;
        }
    }
}

// ---------------------------------------------------------------- recurrence ---
__global__ __launch_bounds__(128) void recur_kernel(
    const float* __restrict__ bias, float* __restrict__ out)
{
    const int b  = blockIdx.x >> 2;
    const int h0 = (blockIdx.x & 3) * 128;
    const int h  = h0 + threadIdx.x;

    const float bb = bias[h];
    float hs = 0.0f, y = 0.0f;

    const float* p  = g_xw + (size_t)b * 262144 + h;
    float*       po = out + ((size_t)b * 512 + h0) * 512;

    __shared__ float buf[128][33];

    for (int tc = 0; tc < 512; tc += 32) {
        #pragma unroll
        for (int j = 0; j < 32; j++) {
            float v = p[(size_t)(tc + j) * 512];
            hs = fmaxf(v + 0.8f * hs * (1.0f - y), 0.0f);
            y  = (hs + bb > 0.0f) ? 1.0f : 0.0f;
            buf[threadIdx.x][j] = y;
        }
        __syncthreads();
        const int r = threadIdx.x >> 5;
        const int c = threadIdx.x & 31;
        #pragma unroll
        for (int rr = 0; rr < 128; rr += 4)
            po[(size_t)(rr + r) * 512 + tc + c] = buf[rr + r][c];
        __syncthreads();
    }
}

// ------------------------------------------------------------------- launch ---
extern "C" void kernel_launch(void* const* d_in, const int* in_sizes, int n_in,
                              void* d_out, int out_size)
{
    const float* x = (const float*)d_in[0];   // (128, 512, 512)
    const float* W = (const float*)d_in[1];   // (512, 512)
    const float* b = (const float*)d_in[2];   // (1, 512)
    float* out = (float*)d_out;               // (128, 512, 512) float32

    cudaFuncSetAttribute(gemm_hmma,
                         cudaFuncAttributeMaxDynamicSharedMemorySize, 4 * STG_B);

    convert_x_kernel<<<dim3(8, 8, 128), 256>>>(x);
    convert_w_kernel<<<dim3(8, 8), 256>>>(W);
    gemm_hmma<<<dim3(4, 512), 256, 4 * STG_B>>>();
    recur_kernel<<<512, 128>>>(b, out);
}